// round 6
// baseline (speedup 1.0000x reference)
#include <cuda_runtime.h>
#include <cuda.h>
#include <math.h>
#include <stdint.h>

// Shapes
//   amplitudes, frequencies : [8, 250, 100] f32
//   out = concat( amp_env [8, 64000, 100], freq_env [8, 250, 100] )  f32
#define B            8
#define FRAMES       250
#define CH           100
#define CTRL_ELEMS   (B * FRAMES * CH)        // 200000
#define T_OUT        64000
#define HOP          256                      // 64000 / 250
#define ENV_ELEMS    (B * T_OUT * CH)         // 51200000
#define SEGS         (B * FRAMES)             // 2000 segments
#define SEG_VEC4     (HOP * (CH / 4))         // 6400 float4 per segment
#define SEG_BYTES    (SEG_VEC4 * 16)          // 102400 bytes per segment
#define UP_THREADS   800                      // 32 rows x 25 float4-groups
#define GRID         296                      // 2 blocks / SM, persistent

// ---------------------------------------------------------------------------
// get_controls math for one (segment, channel) pair.
// ---------------------------------------------------------------------------
__device__ __forceinline__ void controls_math(float a, float f, int c,
                                              float& amp_out, float& freq_out) {
    const float LOG10_F  = 2.302585092994046f;   // ln(10)
    const float MIDI_MAX = 119.21309485364912f;  // 12*(log2 8000-log2 440)+69
    const float NYQ      = 22050.0f;             // SR / 2

    float uf   = 1.0f / (1.0f + expf(-f));
    float freq = 440.0f * exp2f((uf * MIDI_MAX - 69.0f) * (1.0f / 12.0f));

    float sa  = 1.0f / (1.0f + expf(-a));
    float amp = 2.0f * powf(sa, LOG10_F) + 1e-7f;

    float aa = ((freq * (float)(c + 1) < NYQ) ? 1.0f : 0.0f) + 1e-4f;

    amp_out  = amp * aa;
    freq_out = freq;
}

__device__ __forceinline__ uint32_t smem_u32(const void* p) {
    return (uint32_t)__cvta_generic_to_shared(p);
}

// ---------------------------------------------------------------------------
// Persistent fused kernel with TMA bulk stores.
//
// Per segment:
//   1. prefetch controls LDGs (regs only)
//   2. wait_group.read 0 — previous bulk copy has finished READING smem
//   3. controls math -> s_x0/s_x1 (200 threads); barrier
//   4. all 800 threads fill the 100 KB segment tile in smem via STS.128
//      (thread owns fixed channel group c4=tid%25, rows r0+32k)
//   5. fence.proxy.async; barrier; tid 0 issues
//      cp.async.bulk.global.shared::cta.bulk_group (102400 B) + commit
//
// 2 blocks/SM: one block's TMA-drain bubble is hidden by the other block's
// fill + commit, keeping the SM's async store engine continuously busy.
// Global writes go through the TMA path (LTS-capped ~6300 B/cyc chip-wide)
// instead of the per-thread L1tex STG path that capped previous rounds.
// ---------------------------------------------------------------------------
extern __shared__ float4 s_buf4[];             // SEG_VEC4 float4 = 100 KB

__global__ __launch_bounds__(UP_THREADS, 2) void synth_kernel(
        const float* __restrict__ amp_in,
        const float* __restrict__ freq_in,
        float* __restrict__ out,
        float* __restrict__ freq_out) {
    __shared__ __align__(16) float s_x0[CH];
    __shared__ __align__(16) float s_x1[CH];
    __shared__ float sw[HOP];

    const int tid = threadIdx.x;
    const int c4  = tid % 25;                 // channel float4-group (fixed)
    const int r0  = tid / 25;                 // base row within segment

    const bool ctl   = (tid < 200);
    const int  which = ctl ? (tid / CH) : 0;  // 0 -> seg, 1 -> segn
    const int  c     = ctl ? (tid - which * CH) : 0;

    if (tid >= 544) {
        const int r = tid - 544;              // 0..255
        sw[r] = 0.5f - 0.5f * cospif((float)r * (1.0f / 256.0f));
    }

    const uint32_t s_tile = smem_u32(s_buf4);

    for (int s = blockIdx.x; s < SEGS; s += GRID) {
        // (1) Prefetch controls inputs for this segment (registers only;
        //     issued before the smem-reuse wait so LDG latency overlaps it).
        float a_raw = 0.0f, f_raw = 0.0f;
        int idx = 0;
        if (ctl) {
            int ss = s + which;
            if (which && (ss % FRAMES == 0)) ss = s;   // clamp at batch edge
            idx   = ss * CH + c;
            a_raw = amp_in[idx];
            f_raw = freq_in[idx];
        }

        // (2) Previous bulk copy must have finished reading s_buf4.
        if (tid == 0) {
            asm volatile("cp.async.bulk.wait_group.read 0;" ::: "memory");
        }
        __syncthreads();

        // (3) Controls math into smem.
        if (ctl) {
            float amp, frq;
            controls_math(a_raw, f_raw, c, amp, frq);
            if (which) {
                s_x1[c] = amp;
            } else {
                s_x0[c] = amp;
                freq_out[idx] = frq;           // each seg written exactly once
            }
        }
        __syncthreads();

        // (4) Fill the segment tile in smem.
        const float4 x0 = *reinterpret_cast<const float4*>(&s_x0[c4 * 4]);
        const float4 x1 = *reinterpret_cast<const float4*>(&s_x1[c4 * 4]);
        float4 d;
        d.x = x1.x - x0.x;
        d.y = x1.y - x0.y;
        d.z = x1.z - x0.z;
        d.w = x1.w - x0.w;

        float4* o = s_buf4 + tid;
#pragma unroll
        for (int k = 0; k < 8; k++) {
            const float w = sw[r0 + 32 * k];
            float4 v;
            v.x = fmaf(d.x, w, x0.x);
            v.y = fmaf(d.y, w, x0.y);
            v.z = fmaf(d.z, w, x0.z);
            v.w = fmaf(d.w, w, x0.w);
            o[UP_THREADS * k] = v;             // STS.128
        }

        // (5) Make generic-proxy smem writes visible to the async proxy,
        //     then one thread issues the bulk store of the whole tile.
        asm volatile("fence.proxy.async.shared::cta;" ::: "memory");
        __syncthreads();

        if (tid == 0) {
            const char* g_dst = (const char*)out + (size_t)s * SEG_BYTES;
            asm volatile(
                "cp.async.bulk.global.shared::cta.bulk_group [%0], [%1], %2;"
                :: "l"(g_dst), "r"(s_tile), "r"((int)SEG_BYTES)
                : "memory");
            asm volatile("cp.async.bulk.commit_group;" ::: "memory");
        }
    }
    // Outstanding bulk stores drain before grid completion (async proxy is
    // flushed at kernel exit), so no trailing wait is required for output
    // visibility.
}

// ---------------------------------------------------------------------------
extern "C" void kernel_launch(void* const* d_in, const int* in_sizes, int n_in,
                              void* d_out, int out_size) {
    const float* amps  = (const float*)d_in[0];
    const float* freqs = (const float*)d_in[1];
    float* out = (float*)d_out;

    // Opt-in dynamic smem (idempotent; immediate host-side call, not a
    // stream operation, so graph capture is unaffected).
    cudaFuncSetAttribute(synth_kernel,
                         cudaFuncAttributeMaxDynamicSharedMemorySize,
                         SEG_BYTES);

    synth_kernel<<<GRID, UP_THREADS, SEG_BYTES>>>(amps, freqs, out,
                                                  out + ENV_ELEMS);
}

// round 7
// speedup vs baseline: 1.0123x; 1.0123x over previous
#include <cuda_runtime.h>
#include <math.h>

// Shapes
//   amplitudes, frequencies : [8, 250, 100] f32
//   out = concat( amp_env [8, 64000, 100], freq_env [8, 250, 100] )  f32
#define B            8
#define FRAMES       250
#define CH           100
#define CTRL_ELEMS   (B * FRAMES * CH)        // 200000
#define T_OUT        64000
#define HOP          256                      // 64000 / 250
#define ENV_ELEMS    (B * T_OUT * CH)         // 51200000
#define SEGS         (B * FRAMES)             // 2000 segments
#define SEG_VEC4     (HOP * (CH / 4))         // 6400 float4 per segment
#define UP_THREADS   800                      // 32 rows x 25 float4-groups
#define GRID         296                      // 2 blocks / SM, persistent
#define MAX_SEG      7                        // ceil(2000 / 296)

// ---------------------------------------------------------------------------
// get_controls math for one (segment, channel) pair.
//   amp  = (2*sigmoid(a)^ln(10) + 1e-7) * ((freq*harm < SR/2) + 1e-4)
//   freq = 440 * 2^((sigmoid(f)*MIDI_MAX - 69)/12)
// ---------------------------------------------------------------------------
__device__ __forceinline__ void controls_math(float a, float f, int c,
                                              float& amp_out, float& freq_out) {
    const float LOG10_F  = 2.302585092994046f;   // ln(10)
    const float MIDI_MAX = 119.21309485364912f;  // 12*(log2 8000-log2 440)+69
    const float NYQ      = 22050.0f;             // SR / 2

    float uf   = 1.0f / (1.0f + expf(-f));
    float freq = 440.0f * exp2f((uf * MIDI_MAX - 69.0f) * (1.0f / 12.0f));

    float sa  = 1.0f / (1.0f + expf(-a));
    float amp = 2.0f * powf(sa, LOG10_F) + 1e-7f;

    float aa = ((freq * (float)(c + 1) < NYQ) ? 1.0f : 0.0f) + 1e-4f;

    amp_out  = amp * aa;
    freq_out = freq;
}

// ---------------------------------------------------------------------------
// Persistent fused kernel, batched controls:
//
// Phase 1: block bid owns segments s = bid + li*296, li in [0, nseg).
//   All controls for all nseg segments (x0 = amps[s], x1 = amps[s+1 clamped];
//   1400 values max) are computed up-front into s_ctrl by <=2 items/thread,
//   freq outputs written, window table built. ONE barrier.
//
// Phase 2: thread tid owns fixed channel float4-group c4 = tid%25 and base
//   row r0 = tid/25; the 8 window weights are hoisted to registers; then
//   nseg x 8 fully coalesced streaming float4 stores with no barriers, no
//   MUFU, no shared loads in the inner loop:
//     out[row] = x0 + (x1-x0) * w[row],  w[r] = 0.5 - 0.5*cospi(r/256)
// ---------------------------------------------------------------------------
__global__ __launch_bounds__(UP_THREADS, 2) void synth_kernel(
        const float* __restrict__ amp_in,
        const float* __restrict__ freq_in,
        float4* __restrict__ out,
        float* __restrict__ freq_out) {
    __shared__ __align__(16) float s_ctrl[MAX_SEG][2][CH];
    __shared__ float sw[HOP];

    const int tid = threadIdx.x;
    const int bid = blockIdx.x;

    // Number of segments this block owns (6 or 7).
    const int nseg = (SEGS - bid + GRID - 1) / GRID;
    const int n_items = nseg * 2 * CH;        // <= 1400 control values

    // Window table.
    if (tid >= 544) {
        const int r = tid - 544;              // 0..255
        sw[r] = 0.5f - 0.5f * cospif((float)r * (1.0f / 256.0f));
    }

    // Phase 1: all controls for all owned segments (<=2 items per thread).
    for (int i = tid; i < n_items; i += UP_THREADS) {
        const int li    = i / 200;            // local segment index
        const int rem   = i - li * 200;
        const int which = rem / CH;           // 0 -> x0, 1 -> x1
        const int c     = rem - which * CH;   // channel
        const int gseg  = bid + li * GRID;

        int ss = gseg + which;
        if (which && (ss % FRAMES == 0)) ss = gseg;   // clamp at batch edge
        const int idx = ss * CH + c;

        float amp, frq;
        controls_math(amp_in[idx], freq_in[idx], c, amp, frq);
        s_ctrl[li][which][c] = amp;
        if (!which) freq_out[gseg * CH + c] = frq;    // each seg exactly once
    }

    __syncthreads();                           // the ONLY barrier

    // Phase 2: uninterrupted store stream.
    const int c4 = tid % 25;                  // channel float4-group (fixed)
    const int r0 = tid / 25;                  // base row within segment

    float wv[8];
#pragma unroll
    for (int k = 0; k < 8; k++) wv[k] = sw[r0 + 32 * k];

    for (int li = 0; li < nseg; li++) {
        const float4 x0 = *reinterpret_cast<const float4*>(&s_ctrl[li][0][c4 * 4]);
        const float4 x1 = *reinterpret_cast<const float4*>(&s_ctrl[li][1][c4 * 4]);
        float4 d;
        d.x = x1.x - x0.x;
        d.y = x1.y - x0.y;
        d.z = x1.z - x0.z;
        d.w = x1.w - x0.w;

        float4* o = out + (size_t)(bid + li * GRID) * SEG_VEC4 + tid;
#pragma unroll
        for (int k = 0; k < 8; k++) {
            float4 v;
            v.x = fmaf(d.x, wv[k], x0.x);
            v.y = fmaf(d.y, wv[k], x0.y);
            v.z = fmaf(d.z, wv[k], x0.z);
            v.w = fmaf(d.w, wv[k], x0.w);
            __stcs(&o[UP_THREADS * k], v);    // streaming: write-once data
        }
    }
}

// ---------------------------------------------------------------------------
extern "C" void kernel_launch(void* const* d_in, const int* in_sizes, int n_in,
                              void* d_out, int out_size) {
    const float* amps  = (const float*)d_in[0];
    const float* freqs = (const float*)d_in[1];
    float* out = (float*)d_out;

    synth_kernel<<<GRID, UP_THREADS>>>(amps, freqs, (float4*)out,
                                       out + ENV_ELEMS);
}